// round 14
// baseline (speedup 1.0000x reference)
#include <cuda_runtime.h>
#include <cstdint>

// prediction [16,16,16,2048,10] fp32; label [2048] int32 (JAX x64 off).
// Output scalar fp32 = fraction of slices where argmax_c pred == label[b].
//
// Rides the B300 streaming ceiling (~6.4 TB/s measured). Warp-private depth-2
// cp.async pipeline, 512-slice chunks, chunk-strided grid 2960 (= 148*5*4
// exact waves). This round: all hot-loop index math in 32-bit, gmem cursor
// kept as an incrementing pointer, lane offsets hoisted -- cuts ALU-pipe
// pressure between wait_group and the next commit.
#define NC 10
#define NB 2048
#define N_SLICES (16 * 16 * 16 * 2048)        // 8,388,608 = 2^23
#define TPB 256                                // 8 warps
#define CHUNK_SLICES 512                       // per CTA per chunk (2/thread)
#define F4_PER_CHUNK (CHUNK_SLICES * NC / 4)   // 1280 float4 = 20 KB
#define SLICES_PER_WARP 64                     // per chunk
#define F4_PER_WARP 160                        // 64*10/4
#define F4_PER_LANE 5
#define NCHUNK (N_SLICES / CHUNK_SLICES)       // 16384 chunks
#define GRID 2960                              // 148 SMs * 5 CTAs * 4 waves

__device__ unsigned int g_correct_count;   // zero at load; self-reset each run
__device__ unsigned int g_blocks_done;

__device__ __forceinline__ int argmax10(const float* __restrict__ v) {
    float best = v[0];
    int idx = 0;
#pragma unroll
    for (int c = 1; c < NC; c++) {
        if (v[c] > best) { best = v[c]; idx = c; }
    }
    return idx;
}

__device__ __forceinline__ void cp_async16(uint32_t smem_addr, const void* gptr) {
    asm volatile("cp.async.cg.shared.global [%0], [%1], 16;\n"
                 :: "r"(smem_addr), "l"(gptr));
}
__device__ __forceinline__ void cp_async_commit() {
    asm volatile("cp.async.commit_group;\n");
}
template <int N>
__device__ __forceinline__ void cp_async_wait() {
    asm volatile("cp.async.wait_group %0;\n" :: "n"(N));
}

__global__ __launch_bounds__(TPB) void accuracy_fused_kernel(
    const float* __restrict__ pred,
    const int* __restrict__ label,
    float* __restrict__ out)
{
    __shared__ float4 tile[2][F4_PER_CHUNK];   // 2 x 20 KB, warp-partitioned
    __shared__ unsigned int warp_sums[TPB / 32];

    const int tid  = threadIdx.x;
    const int lane = tid & 31;
    const int wid  = tid >> 5;
    const int bid  = blockIdx.x;

    // This warp's staging regions; lane-fixed smem targets precomputed.
    float4* const wtile0 = &tile[0][wid * F4_PER_WARP];
    float4* const wtile1 = &tile[1][wid * F4_PER_WARP];
    uint32_t sdst[2];
    sdst[0] = (uint32_t)__cvta_generic_to_shared(wtile0) + (uint32_t)lane * 16u;
    sdst[1] = (uint32_t)__cvta_generic_to_shared(wtile1) + (uint32_t)lane * 16u;

    // Gmem cursor for this warp+lane: float4 index bid*1280 + wid*160 + lane.
    // Max index 16383*1280+1280 = 21.0M (fits int); advances by GRID*1280.
    const float4* gcur = reinterpret_cast<const float4*>(pred)
                       + (bid * F4_PER_CHUNK + wid * F4_PER_WARP + lane);
    const int gstride = GRID * F4_PER_CHUNK;   // 3,788,800 (fits int)

    // Label pair: chunk mod 4 == bid mod 4 is constant per CTA (GRID%4==0).
    int lab0, lab1;
    {
        int2 lp = *reinterpret_cast<const int2*>(
            label + ((bid & 3) * CHUNK_SLICES + wid * SLICES_PER_WARP + 2 * lane));
        lab0 = lp.x;
        lab1 = lp.y;
    }

    unsigned int my_correct = 0;

    // Prologue: prefetch chunk bid into buf 0 (5 coalesced 16B cp.async/lane).
#pragma unroll
    for (int j = 0; j < F4_PER_LANE; j++) {
        cp_async16(sdst[0] + (uint32_t)(j * 32) * 16u, gcur + j * 32);
    }
    cp_async_commit();

    // Number of chunks this CTA owns: bid < 16384 - 5*2960=1584? ceil div.
    const int niter = (NCHUNK - 1 - bid) / GRID + 1;   // 5 or 6

    int iter = 0;
    for (int r = 0; r < niter; r++, iter++) {
        const int cur = iter & 1;
        if (r + 1 < niter) {
            const float4* src = gcur + gstride;        // next chunk, same lane
#pragma unroll
            for (int j = 0; j < F4_PER_LANE; j++) {
                cp_async16(sdst[cur ^ 1] + (uint32_t)(j * 32) * 16u, src + j * 32);
            }
            cp_async_commit();
            cp_async_wait<1>();   // current chunk's group complete (this lane)
        } else {
            cp_async_wait<0>();
        }
        gcur += gstride;
        __syncwarp();             // warp's staged data visible to all lanes

        // Lane owns slices 2*lane, 2*lane+1 of the warp's 64:
        // float4 [5*lane, 5*lane+5). 80 B/lane stride -> conflict-free LDS.128.
        const float4* wt = cur ? wtile1 : wtile0;
        float4 q[5];
#pragma unroll
        for (int j = 0; j < 5; j++) q[j] = wt[5 * lane + j];

        float a[NC] = { q[0].x, q[0].y, q[0].z, q[0].w,
                        q[1].x, q[1].y, q[1].z, q[1].w,
                        q[2].x, q[2].y };
        float b[NC] = { q[2].z, q[2].w,
                        q[3].x, q[3].y, q[3].z, q[3].w,
                        q[4].x, q[4].y, q[4].z, q[4].w };

        const int i0 = argmax10(a);
        const int i1 = argmax10(b);

        my_correct += (i0 == lab0) ? 1u : 0u;
        my_correct += (i1 == lab1) ? 1u : 0u;

        __syncwarp();             // reads done before this buffer is re-filled
    }

    // Warp redux -> block reduce -> one atomic per block (2960 total, exact).
    unsigned int warp_total = __reduce_add_sync(0xFFFFFFFFu, my_correct);
    if (lane == 0) warp_sums[wid] = warp_total;
    __syncthreads();

    if (tid == 0) {
        unsigned int s = 0;
#pragma unroll
        for (int w = 0; w < TPB / 32; w++) s += warp_sums[w];
        atomicAdd(&g_correct_count, s);
        __threadfence();
        unsigned int done = atomicAdd(&g_blocks_done, 1u);
        if (done == GRID - 1) {
            unsigned int total = atomicAdd(&g_correct_count, 0u);   // L2 read
            out[0] = (float)total * (1.0f / (float)N_SLICES);       // exact /2^23
            g_correct_count = 0u;                                   // replay-safe
            g_blocks_done = 0u;
            __threadfence();
        }
    }
}

extern "C" void kernel_launch(void* const* d_in, const int* in_sizes, int n_in,
                              void* d_out, int out_size) {
    const float* pred = (const float*)d_in[0];
    const int* label = (const int*)d_in[1];
    float* out = (float*)d_out;

    accuracy_fused_kernel<<<GRID, TPB>>>(pred, label, out);
}

// round 15
// speedup vs baseline: 1.0466x; 1.0466x over previous
#include <cuda_runtime.h>
#include <cstdint>

// prediction [16,16,16,2048,10] fp32; label [2048] int32 (JAX x64 off).
// Output scalar fp32 = fraction of slices where argmax_c pred == label[b].
//
// FINAL (R13 config, best measured: 53.28 us, 6.38 TB/s ~= B300 streaming
// ceiling; ideal 51.7 us). Warp-private depth-2 cp.async pipeline, 512-slice
// chunks, chunk-strided grid 2960 = 148 SMs * 5 CTAs * 4 exact waves.
// Addresses computed independently per iteration (no loop-carried pointer:
// R14 showed that serializing prefetch addressing costs ~2-4 us).
#define NC 10
#define NB 2048
#define N_SLICES (16 * 16 * 16 * 2048)        // 8,388,608 = 2^23
#define TPB 256                                // 8 warps
#define CHUNK_SLICES 512                       // per CTA per chunk (2/thread)
#define F4_PER_CHUNK (CHUNK_SLICES * NC / 4)   // 1280 float4 = 20 KB
#define SLICES_PER_WARP 64                     // per chunk
#define F4_PER_WARP 160                        // 64*10/4
#define F4_PER_LANE 5
#define NCHUNK (N_SLICES / CHUNK_SLICES)       // 16384 chunks
#define GRID 2960                              // 148 SMs * 5 CTAs * 4 waves

__device__ unsigned int g_correct_count;   // zero at load; self-reset each run
__device__ unsigned int g_blocks_done;

__device__ __forceinline__ int argmax10(const float* __restrict__ v) {
    float best = v[0];
    int idx = 0;
#pragma unroll
    for (int c = 1; c < NC; c++) {
        if (v[c] > best) { best = v[c]; idx = c; }
    }
    return idx;
}

__device__ __forceinline__ void cp_async16(uint32_t smem_addr, const void* gptr) {
    asm volatile("cp.async.cg.shared.global [%0], [%1], 16;\n"
                 :: "r"(smem_addr), "l"(gptr));
}
__device__ __forceinline__ void cp_async_commit() {
    asm volatile("cp.async.commit_group;\n");
}
template <int N>
__device__ __forceinline__ void cp_async_wait() {
    asm volatile("cp.async.wait_group %0;\n" :: "n"(N));
}

__global__ __launch_bounds__(TPB) void accuracy_fused_kernel(
    const float* __restrict__ pred,
    const int* __restrict__ label,
    float* __restrict__ out)
{
    __shared__ float4 tile[2][F4_PER_CHUNK];   // 2 x 20 KB, warp-partitioned
    __shared__ unsigned int warp_sums[TPB / 32];

    const int tid  = threadIdx.x;
    const int lane = tid & 31;
    const int wid  = tid >> 5;
    const int bid  = blockIdx.x;

    // This warp's staging regions.
    float4* const wtile0 = &tile[0][wid * F4_PER_WARP];
    float4* const wtile1 = &tile[1][wid * F4_PER_WARP];
    uint32_t waddr[2];
    waddr[0] = (uint32_t)__cvta_generic_to_shared(wtile0);
    waddr[1] = (uint32_t)__cvta_generic_to_shared(wtile1);

    const float4* const gpred = reinterpret_cast<const float4*>(pred);

    // Chunk gc covers slices gc*512; this thread's slices are
    //   gc*512 + wid*64 + 2*lane (+1). Batch = that mod 2048.
    // gc = bid + k*GRID and GRID % 4 == 0  ->  gc % 4 == bid % 4 constant.
    int lab0, lab1;
    {
        int2 lp = *reinterpret_cast<const int2*>(
            label + ((bid & 3) * CHUNK_SLICES + wid * SLICES_PER_WARP + 2 * lane));
        lab0 = lp.x;
        lab1 = lp.y;
    }

    unsigned int my_correct = 0;

    // Prologue: prefetch chunk bid into buf 0 (5 coalesced 16B cp.async/lane).
    {
        const float4* src = gpred + (long long)bid * F4_PER_CHUNK + wid * F4_PER_WARP;
#pragma unroll
        for (int j = 0; j < F4_PER_LANE; j++) {
            cp_async16(waddr[0] + (uint32_t)(j * 32 + lane) * 16u,
                       src + j * 32 + lane);
        }
        cp_async_commit();
    }

    int iter = 0;
    for (long long gc = bid; gc < NCHUNK; gc += GRID, iter++) {
        const int cur = iter & 1;
        const long long gn = gc + GRID;
        if (gn < NCHUNK) {
            const float4* src = gpred + gn * F4_PER_CHUNK + wid * F4_PER_WARP;
            const uint32_t dst = waddr[cur ^ 1];
#pragma unroll
            for (int j = 0; j < F4_PER_LANE; j++) {
                cp_async16(dst + (uint32_t)(j * 32 + lane) * 16u,
                           src + j * 32 + lane);
            }
            cp_async_commit();
            cp_async_wait<1>();   // current chunk's group complete (this lane)
        } else {
            cp_async_wait<0>();
        }
        __syncwarp();             // warp's staged data visible to all lanes

        // Lane owns slices 2*lane, 2*lane+1 of the warp's 64:
        // float4 [5*lane, 5*lane+5). 80 B/lane stride -> conflict-free LDS.128.
        const float4* wt = cur ? wtile1 : wtile0;
        float4 q[5];
#pragma unroll
        for (int j = 0; j < 5; j++) q[j] = wt[5 * lane + j];

        float a[NC] = { q[0].x, q[0].y, q[0].z, q[0].w,
                        q[1].x, q[1].y, q[1].z, q[1].w,
                        q[2].x, q[2].y };
        float b[NC] = { q[2].z, q[2].w,
                        q[3].x, q[3].y, q[3].z, q[3].w,
                        q[4].x, q[4].y, q[4].z, q[4].w };

        const int i0 = argmax10(a);
        const int i1 = argmax10(b);

        my_correct += (i0 == lab0) ? 1u : 0u;
        my_correct += (i1 == lab1) ? 1u : 0u;

        __syncwarp();             // reads done before this buffer is re-filled
    }

    // Warp redux -> block reduce -> one atomic per block (2960 total, exact).
    unsigned int warp_total = __reduce_add_sync(0xFFFFFFFFu, my_correct);
    if (lane == 0) warp_sums[wid] = warp_total;
    __syncthreads();

    if (tid == 0) {
        unsigned int s = 0;
#pragma unroll
        for (int w = 0; w < TPB / 32; w++) s += warp_sums[w];
        atomicAdd(&g_correct_count, s);
        __threadfence();
        unsigned int done = atomicAdd(&g_blocks_done, 1u);
        if (done == GRID - 1) {
            unsigned int total = atomicAdd(&g_correct_count, 0u);   // L2 read
            out[0] = (float)total * (1.0f / (float)N_SLICES);       // exact /2^23
            g_correct_count = 0u;                                   // replay-safe
            g_blocks_done = 0u;
            __threadfence();
        }
    }
}

extern "C" void kernel_launch(void* const* d_in, const int* in_sizes, int n_in,
                              void* d_out, int out_size) {
    const float* pred = (const float*)d_in[0];
    const int* label = (const int*)d_in[1];
    float* out = (float*)d_out;

    accuracy_fused_kernel<<<GRID, TPB>>>(pred, label, out);
}

// round 16
// speedup vs baseline: 1.0485x; 1.0018x over previous
#include <cuda_runtime.h>
#include <cstdint>

// prediction [16,16,16,2048,10] fp32; label [2048] int32 (JAX x64 off).
// Output scalar fp32 = fraction of slices where argmax_c pred == label[b].
//
// FINAL converged kernel. Best measured: 52.90 us bench / 51.30 us ncu,
// 6.61 TB/s (83.5% DRAM) -- the B300 streaming ceiling for this pattern
// (steady-state ideal 50.8 us). Structure: warp-private depth-2 cp.async
// pipeline, 512-slice chunks, chunk-strided grid 2960 = 148 SMs * 5 CTAs *
// 4 exact waves. Per-iteration independent address computation (R14 showed a
// loop-carried prefetch pointer costs 2-4 us). Exact integer count path:
// ballot-free register accumulate -> redux.sync -> one atomic per CTA ->
// last-block finalize with self-resetting counters (graph-replay safe).
#define NC 10
#define NB 2048
#define N_SLICES (16 * 16 * 16 * 2048)        // 8,388,608 = 2^23
#define TPB 256                                // 8 warps
#define CHUNK_SLICES 512                       // per CTA per chunk (2/thread)
#define F4_PER_CHUNK (CHUNK_SLICES * NC / 4)   // 1280 float4 = 20 KB
#define SLICES_PER_WARP 64                     // per chunk
#define F4_PER_WARP 160                        // 64*10/4
#define F4_PER_LANE 5
#define NCHUNK (N_SLICES / CHUNK_SLICES)       // 16384 chunks
#define GRID 2960                              // 148 SMs * 5 CTAs * 4 waves

__device__ unsigned int g_correct_count;   // zero at load; self-reset each run
__device__ unsigned int g_blocks_done;

__device__ __forceinline__ int argmax10(const float* __restrict__ v) {
    float best = v[0];
    int idx = 0;
#pragma unroll
    for (int c = 1; c < NC; c++) {
        if (v[c] > best) { best = v[c]; idx = c; }
    }
    return idx;
}

__device__ __forceinline__ void cp_async16(uint32_t smem_addr, const void* gptr) {
    asm volatile("cp.async.cg.shared.global [%0], [%1], 16;\n"
                 :: "r"(smem_addr), "l"(gptr));
}
__device__ __forceinline__ void cp_async_commit() {
    asm volatile("cp.async.commit_group;\n");
}
template <int N>
__device__ __forceinline__ void cp_async_wait() {
    asm volatile("cp.async.wait_group %0;\n" :: "n"(N));
}

__global__ __launch_bounds__(TPB) void accuracy_fused_kernel(
    const float* __restrict__ pred,
    const int* __restrict__ label,
    float* __restrict__ out)
{
    __shared__ float4 tile[2][F4_PER_CHUNK];   // 2 x 20 KB, warp-partitioned
    __shared__ unsigned int warp_sums[TPB / 32];

    const int tid  = threadIdx.x;
    const int lane = tid & 31;
    const int wid  = tid >> 5;
    const int bid  = blockIdx.x;

    // This warp's staging regions.
    float4* const wtile0 = &tile[0][wid * F4_PER_WARP];
    float4* const wtile1 = &tile[1][wid * F4_PER_WARP];
    uint32_t waddr[2];
    waddr[0] = (uint32_t)__cvta_generic_to_shared(wtile0);
    waddr[1] = (uint32_t)__cvta_generic_to_shared(wtile1);

    const float4* const gpred = reinterpret_cast<const float4*>(pred);

    // Chunk gc covers slices gc*512; this thread's slices are
    //   gc*512 + wid*64 + 2*lane (+1). Batch = that mod 2048.
    // gc = bid + k*GRID and GRID % 4 == 0  ->  gc % 4 == bid % 4 constant.
    int lab0, lab1;
    {
        int2 lp = *reinterpret_cast<const int2*>(
            label + ((bid & 3) * CHUNK_SLICES + wid * SLICES_PER_WARP + 2 * lane));
        lab0 = lp.x;
        lab1 = lp.y;
    }

    unsigned int my_correct = 0;

    // Prologue: prefetch chunk bid into buf 0 (5 coalesced 16B cp.async/lane).
    {
        const float4* src = gpred + (long long)bid * F4_PER_CHUNK + wid * F4_PER_WARP;
#pragma unroll
        for (int j = 0; j < F4_PER_LANE; j++) {
            cp_async16(waddr[0] + (uint32_t)(j * 32 + lane) * 16u,
                       src + j * 32 + lane);
        }
        cp_async_commit();
    }

    int iter = 0;
    for (long long gc = bid; gc < NCHUNK; gc += GRID, iter++) {
        const int cur = iter & 1;
        const long long gn = gc + GRID;
        if (gn < NCHUNK) {
            const float4* src = gpred + gn * F4_PER_CHUNK + wid * F4_PER_WARP;
            const uint32_t dst = waddr[cur ^ 1];
#pragma unroll
            for (int j = 0; j < F4_PER_LANE; j++) {
                cp_async16(dst + (uint32_t)(j * 32 + lane) * 16u,
                           src + j * 32 + lane);
            }
            cp_async_commit();
            cp_async_wait<1>();   // current chunk's group complete (this lane)
        } else {
            cp_async_wait<0>();
        }
        __syncwarp();             // warp's staged data visible to all lanes

        // Lane owns slices 2*lane, 2*lane+1 of the warp's 64:
        // float4 [5*lane, 5*lane+5). 80 B/lane stride -> conflict-free LDS.128.
        const float4* wt = cur ? wtile1 : wtile0;
        float4 q[5];
#pragma unroll
        for (int j = 0; j < 5; j++) q[j] = wt[5 * lane + j];

        float a[NC] = { q[0].x, q[0].y, q[0].z, q[0].w,
                        q[1].x, q[1].y, q[1].z, q[1].w,
                        q[2].x, q[2].y };
        float b[NC] = { q[2].z, q[2].w,
                        q[3].x, q[3].y, q[3].z, q[3].w,
                        q[4].x, q[4].y, q[4].z, q[4].w };

        const int i0 = argmax10(a);
        const int i1 = argmax10(b);

        my_correct += (i0 == lab0) ? 1u : 0u;
        my_correct += (i1 == lab1) ? 1u : 0u;

        __syncwarp();             // reads done before this buffer is re-filled
    }

    // Warp redux -> block reduce -> one atomic per block (2960 total, exact).
    unsigned int warp_total = __reduce_add_sync(0xFFFFFFFFu, my_correct);
    if (lane == 0) warp_sums[wid] = warp_total;
    __syncthreads();

    if (tid == 0) {
        unsigned int s = 0;
#pragma unroll
        for (int w = 0; w < TPB / 32; w++) s += warp_sums[w];
        atomicAdd(&g_correct_count, s);
        __threadfence();
        unsigned int done = atomicAdd(&g_blocks_done, 1u);
        if (done == GRID - 1) {
            unsigned int total = atomicAdd(&g_correct_count, 0u);   // L2 read
            out[0] = (float)total * (1.0f / (float)N_SLICES);       // exact /2^23
            g_correct_count = 0u;                                   // replay-safe
            g_blocks_done = 0u;
            __threadfence();
        }
    }
}

extern "C" void kernel_launch(void* const* d_in, const int* in_sizes, int n_in,
                              void* d_out, int out_size) {
    const float* pred = (const float*)d_in[0];
    const int* label = (const int*)d_in[1];
    float* out = (float*)d_out;

    accuracy_fused_kernel<<<GRID, TPB>>>(pred, label, out);
}